// round 15
// baseline (speedup 1.0000x reference)
#include <cuda_runtime.h>
#include <cstdint>
#include <cstddef>

typedef unsigned long long ull;

// 2-layer LSTM, B=512 T=1024 I=80 H=160, fp32.
// Kernel 1 (xproj): X0[t][row][b] = x @ W_ih0^T + b_ih0 + b_hh0.
// Kernel 2 (lstm2): persistent 8-CTA-cluster recurrence, 640 threads
//   (20 warps, 5/SMSP). Warp w owns gate row w of each quarter (4 rows,
//   one h row per layer). Weight slices SMEM-resident; h replicated per
//   rank (k-pair layout); h0 double-buffered. 2 rendezvous per step
//   (R0, R1; count 8; stores -> __syncthreads -> tid0 arrive.release).

#define HDIM   160
#define IDIM   80
#define TSTEPS 1024
#define BATCH  512
#define CLUSTER 8
#define HS 20
#define GS 80
#define NB 32
#define NTH 640        // 20 warps
#define NCLUS 16
#define GRIDN (NCLUS*CLUSTER)

__device__ float g_X0[(size_t)TSTEPS * 640 * BATCH];

// ---- lstm2 shared layout (float offsets) ----
#define OFF_W0   0        // W_hh0 slice [GS][HDIM]
#define OFF_WH1  12800    // W_hh1 slice [GS][HDIM]
#define OFF_WI1  25600    // W_ih1 slice [GS][HDIM]
#define OFF_H0A  38400    // h0 buf0, k-pairs [80][NB] (ull)
#define OFF_H0B  43520    // h0 buf1
#define OFF_H1   48640    // h1 (single buffer)
#define OFF_WOUT 53760    // W_out [160]
#define OFF_B1   53920    // fused bias layer1 slice [GS]
#define OFF_MBAR 54000    // 2 mbarriers (u64)
#define SMEM_FLOATS 54008
#define SMEM_BYTES (SMEM_FLOATS*4)   // 216032 B

#define MB_R0 (OFF_MBAR*4 + 0)   // h0(t) published (count 8)
#define MB_R1 (OFF_MBAR*4 + 8)   // h1(t) published (count 8)

__device__ __forceinline__ uint32_t smem_u32(const void* p){
    uint32_t a;
    asm("{ .reg .u64 t; cvta.to.shared.u64 t, %1; cvt.u32.u64 %0, t; }"
        : "=r"(a) : "l"(p));
    return a;
}
__device__ __forceinline__ uint32_t mapa_rank(uint32_t addr, uint32_t r){
    uint32_t d;
    asm("mapa.shared::cluster.u32 %0, %1, %2;" : "=r"(d) : "r"(addr), "r"(r));
    return d;
}
__device__ __forceinline__ void st_cluster_f32(uint32_t addr, float v){
    asm volatile("st.shared::cluster.f32 [%0], %1;" :: "r"(addr), "f"(v));
}
__device__ __forceinline__ uint32_t ctarank(){
    uint32_t r; asm("mov.u32 %0, %%cluster_ctarank;" : "=r"(r)); return r;
}
__device__ __forceinline__ void mbar_init(uint32_t addr, uint32_t cnt){
    asm volatile("mbarrier.init.shared.b64 [%0], %1;" :: "r"(addr), "r"(cnt)
                 : "memory");
}
__device__ __forceinline__ void mbar_arrive_all(uint32_t local_addr){
    #pragma unroll
    for (uint32_t r = 0; r < CLUSTER; r++){
        uint32_t ra = mapa_rank(local_addr, r);
        asm volatile(
            "mbarrier.arrive.release.cluster.shared::cluster.b64 _, [%0];"
            :: "r"(ra) : "memory");
    }
}
__device__ __forceinline__ void mbar_wait(uint32_t addr, uint32_t parity){
    uint32_t done;
    asm volatile(
        "{ .reg .pred p;\n\t"
        "mbarrier.try_wait.parity.acquire.cluster.shared::cta.b64 p, [%1], %2;\n\t"
        "selp.b32 %0, 1, 0, p; }"
        : "=r"(done) : "r"(addr), "r"(parity) : "memory");
    while (!done){
        asm volatile(
            "{ .reg .pred p;\n\t"
            "mbarrier.try_wait.parity.acquire.cluster.shared::cta.b64 p, [%1], %2, 0x989680;\n\t"
            "selp.b32 %0, 1, 0, p; }"
            : "=r"(done) : "r"(addr), "r"(parity) : "memory");
    }
}

__device__ __forceinline__ void ffma2(ull &a, ull b, ull c){
    asm("fma.rn.f32x2 %0, %1, %2, %0;" : "+l"(a) : "l"(b), "l"(c));
}
__device__ __forceinline__ ull pack2(float lo, float hi){
    ull r; asm("mov.b64 %0, {%1,%2};" : "=l"(r) : "f"(lo), "f"(hi)); return r;
}
__device__ __forceinline__ float sum2(ull v){
    float lo, hi; asm("mov.b64 {%0,%1}, %2;" : "=f"(lo), "=f"(hi) : "l"(v));
    return lo + hi;
}
__device__ __forceinline__ float sigm(float x){
    return __fdividef(1.0f, 1.0f + __expf(-x));
}
__device__ __forceinline__ float tanhfast(float x){
    return 2.0f*__fdividef(1.0f, 1.0f + __expf(-2.0f*x)) - 1.0f;
}

// acc[q] (f32x2 even/odd-k partials) += W[(q*HS+w)][:] . h[:], K elements.
// W warp-uniform LDS.128, h lane LDS.64, next iter's loads pipelined.
template<int K>
__device__ __forceinline__ void mm4h(ull acc[4], const float* __restrict__ Wsm,
                                     int w, const ull* __restrict__ hp){
    const ulonglong2* W[4];
    #pragma unroll
    for (int q = 0; q < 4; q++)
        W[q] = reinterpret_cast<const ulonglong2*>(Wsm + (q*HS + w)*K);
    ull h01 = hp[0], h23 = hp[NB];
    ulonglong2 wv[4];
    #pragma unroll
    for (int q = 0; q < 4; q++) wv[q] = W[q][0];
    #pragma unroll 8
    for (int kk = 0; kk < K/4; kk++){
        ull n01 = 0, n23 = 0;
        ulonglong2 nw[4];
        if (kk + 1 < K/4){
            n01 = hp[(2*kk+2)*NB]; n23 = hp[(2*kk+3)*NB];
            #pragma unroll
            for (int q = 0; q < 4; q++) nw[q] = W[q][kk+1];
        }
        #pragma unroll
        for (int q = 0; q < 4; q++){
            ffma2(acc[q], wv[q].x, h01);
            ffma2(acc[q], wv[q].y, h23);
        }
        h01 = n01; h23 = n23;
        #pragma unroll
        for (int q = 0; q < 4; q++) wv[q] = nw[q];
    }
}

// ============ kernel 1: X0 = x @ W_ih0^T + bias ============
#define XP_THREADS 256
#define XP_LD 132

__global__ __launch_bounds__(XP_THREADS)
void xproj_kernel(const float* __restrict__ x,
                  const float* __restrict__ Wih0,
                  const float* __restrict__ bih0,
                  const float* __restrict__ bhh0)
{
    extern __shared__ float s[];
    float* WT = s;
    float* XT = s + IDIM*XP_LD;
    const int t = blockIdx.z;
    const int rowbase = blockIdx.y * 128;
    const int bbase   = blockIdx.x * 128;

    for (int idx = threadIdx.x; idx < 128*IDIM; idx += XP_THREADS){
        int r = idx / IDIM, k = idx - r*IDIM;
        WT[k*XP_LD + r] = Wih0[(rowbase + r)*IDIM + k];
    }
    for (int idx = threadIdx.x; idx < 128*IDIM; idx += XP_THREADS){
        int b = idx / IDIM, k = idx - b*IDIM;
        XT[k*XP_LD + b] = x[(size_t)(bbase + b)*(TSTEPS*IDIM)
                            + (size_t)t*IDIM + k];
    }
    __syncthreads();

    const int brow = threadIdx.x >> 4;
    const int bcol = threadIdx.x & 15;
    float acc[8][8] = {};
    for (int k = 0; k < IDIM; k++){
        float wr[8], xr[8];
        #pragma unroll
        for (int i = 0; i < 8; i++) wr[i] = WT[k*XP_LD + brow + 16*i];
        #pragma unroll
        for (int j = 0; j < 8; j++) xr[j] = XT[k*XP_LD + bcol + 16*j];
        #pragma unroll
        for (int i = 0; i < 8; i++)
            #pragma unroll
            for (int j = 0; j < 8; j++)
                acc[i][j] += wr[i]*xr[j];
    }
    #pragma unroll
    for (int i = 0; i < 8; i++){
        int row = rowbase + brow + 16*i;
        float bias = bih0[row] + bhh0[row];
        float* dst = g_X0 + ((size_t)t*640 + row)*BATCH + bbase;
        #pragma unroll
        for (int j = 0; j < 8; j++)
            dst[bcol + 16*j] = acc[i][j] + bias;
    }
}

// ============ kernel 2: recurrence ============
__global__ void __cluster_dims__(CLUSTER,1,1) __launch_bounds__(NTH,1)
lstm2_kernel(const float* __restrict__ Whh0,
             const float* __restrict__ Wih1, const float* __restrict__ Whh1,
             const float* __restrict__ bih1, const float* __restrict__ bhh1,
             const float* __restrict__ Wout, const float* __restrict__ bout,
             float* __restrict__ out)
{
    extern __shared__ float sm[];
    const int tid  = threadIdx.x;
    const int lane = tid & 31;
    const int w    = tid >> 5;        // 0..19; owns gate row w per quarter
    const uint32_t rank = ctarank();
    const int cidx = blockIdx.x / CLUSTER;
    const int b0g  = cidx * NB;
    const int hb   = (int)rank * HS;
    const uint32_t smb = smem_u32(sm);

    // persistent weight slices
    for (int idx = tid; idx < GS*HDIM; idx += NTH){
        int lr = idx / HDIM, k = idx - lr*HDIM;
        int q = lr / HS, j = lr - q*HS;
        int grow = q*HDIM + hb + j;           // pytorch gate order i,f,g,o
        sm[OFF_W0  + idx] = Whh0[grow*HDIM + k];
        sm[OFF_WH1 + idx] = Whh1[grow*HDIM + k];
        sm[OFF_WI1 + idx] = Wih1[grow*HDIM + k];
    }
    for (int idx = tid; idx < GS; idx += NTH){
        int q = idx / HS, j = idx - q*HS;
        int grow = q*HDIM + hb + j;
        sm[OFF_B1 + idx] = bih1[grow] + bhh1[grow];
    }
    for (int idx = tid; idx < HDIM; idx += NTH) sm[OFF_WOUT + idx] = Wout[idx];
    for (int idx = tid; idx < 3*HDIM*NB; idx += NTH) sm[OFF_H0A + idx] = 0.0f;
    if (tid == 0){
        mbar_init(smb + MB_R0, CLUSTER);
        mbar_init(smb + MB_R1, CLUSTER);
    }
    float c0 = 0.f, c1 = 0.f;
    __syncthreads();
    asm volatile("barrier.cluster.arrive.aligned;" ::: "memory");
    asm volatile("barrier.cluster.wait.aligned;"   ::: "memory");
    // prime R1 phase 0 (h1(-1)=0 already staged)
    if (tid == 0) mbar_arrive_all(smb + MB_R1);

    // this thread's h element: row g = hb+w, batch lane.
    // k-pair float offset within a buffer: ((g>>1)*NB + lane)*2 + (g&1)
    const int g = hb + w;
    const uint32_t eoff = (uint32_t)(((g >> 1)*NB + lane)*2 + (g & 1))*4u;
    const uint32_t oA = smb + OFF_H0A*4 + eoff;
    const uint32_t oB = smb + OFF_H0B*4 + eoff;
    const uint32_t o1 = smb + OFF_H1*4  + eoff;

    float b1r[4];
    #pragma unroll
    for (int q = 0; q < 4; q++) b1r[q] = sm[OFF_B1 + q*HS + w];

    // X0 row pointers for this thread's 4 gate rows
    const float* xp[4];
    #pragma unroll
    for (int q = 0; q < 4; q++){
        int grow = q*HDIM + hb + w;
        xp[q] = g_X0 + (size_t)grow*BATCH + b0g + lane;
    }

    const ull* h0A = reinterpret_cast<const ull*>(&sm[OFF_H0A]) + lane;
    const ull* h0B = reinterpret_cast<const ull*>(&sm[OFF_H0B]) + lane;
    const ull* hp1 = reinterpret_cast<const ull*>(&sm[OFF_H1])  + lane;
    const ull* wo  = reinterpret_cast<const ull*>(&sm[OFF_WOUT]);
    const float boutv = bout[0];
    float* const orow = out + (size_t)(b0g + lane)*TSTEPS;

    for (int t = 0; t < TSTEPS; t++){
        const uint32_t par = (uint32_t)(t & 1);
        const int p = t & 1;
        const ull* hp0_old = p ? h0A : h0B;
        const ull* hp0_new = p ? h0B : h0A;
        const uint32_t ow  = p ? oB : oA;

        // 1: X0 gate seeds (LDG in flight through segment 2)
        float xg[4];
        #pragma unroll
        for (int q = 0; q < 4; q++) xg[q] = xp[q][(size_t)t*640*BATCH];

        // 2: layer-0 recurrent, reads h0(t-1)
        ull acc[4];
        #pragma unroll
        for (int q = 0; q < 4; q++) acc[q] = pack2(xg[q], 0.f);
        mm4h<HDIM>(acc, &sm[OFF_W0], w, hp0_old);

        // 3: h1(t-1) ready (published at end of step t-1; hidden behind 2)
        mbar_wait(smb + MB_R1, par);

        // 4: output head for t-1 (reads h1(t-1); ordered before h1(t)
        //    stores via this CTA's R0 participation below)
        if (w == 0 && t > 0){
            ull s0 = pack2(boutv, 0.f), s1 = 0, s2 = 0, s3 = 0;
            #pragma unroll 10
            for (int pp = 0; pp < HDIM/2; pp += 4){
                ffma2(s0, wo[pp  ], hp1[(pp  )*NB]);
                ffma2(s1, wo[pp+1], hp1[(pp+1)*NB]);
                ffma2(s2, wo[pp+2], hp1[(pp+2)*NB]);
                ffma2(s3, wo[pp+3], hp1[(pp+3)*NB]);
            }
            float y = (sum2(s0) + sum2(s1)) + (sum2(s2) + sum2(s3));
            orow[t-1] = fmaxf(y, 0.0f);
        }

        // 5: layer-1 recurrent W_hh1 . h1(t-1) — precedes h0 publish
        ull a1c[4];
        #pragma unroll
        for (int q = 0; q < 4; q++) a1c[q] = pack2(b1r[q], 0.f);
        mm4h<HDIM>(a1c, &sm[OFF_WH1], w, hp1);

        // 6: layer-0 activations (one h row per thread)
        float hn0;
        {
            float gi = sigm(sum2(acc[0])), gf = sigm(sum2(acc[1]));
            float gg = tanhfast(sum2(acc[2])), go = sigm(sum2(acc[3]));
            c0 = gf*c0 + gi*gg;  hn0 = go*tanhfast(c0);
        }

        // 7: publish h0(t) -> buf t&1 (stores -> sync -> tid0 arrive)
        #pragma unroll
        for (uint32_t r = 0; r < CLUSTER; r++)
            st_cluster_f32(mapa_rank(ow, r), hn0);
        __syncthreads();
        if (tid == 0) mbar_arrive_all(smb + MB_R0);

        // 8: h0(t) visible everywhere
        mbar_wait(smb + MB_R0, par);

        // 9: W_ih1 . h0(t)
        mm4h<HDIM>(a1c, &sm[OFF_WI1], w, hp0_new);

        // 10: layer-1 activations
        float hn1;
        {
            float gi = sigm(sum2(a1c[0])), gf = sigm(sum2(a1c[1]));
            float gg = tanhfast(sum2(a1c[2])), go = sigm(sum2(a1c[3]));
            c1 = gf*c1 + gi*gg;  hn1 = go*tanhfast(c1);
        }

        // 11: publish h1(t) (single buffer; WAR covered by R0(t))
        #pragma unroll
        for (uint32_t r = 0; r < CLUSTER; r++)
            st_cluster_f32(mapa_rank(o1, r), hn1);
        __syncthreads();
        if (tid == 0) mbar_arrive_all(smb + MB_R1);
    }

    // final head: h1(T-1)
    mbar_wait(smb + MB_R1, (uint32_t)(TSTEPS & 1));
    if (w == 0){
        ull s0 = pack2(boutv, 0.f), s1 = 0, s2 = 0, s3 = 0;
        #pragma unroll 10
        for (int pp = 0; pp < HDIM/2; pp += 4){
            ffma2(s0, wo[pp  ], hp1[(pp  )*NB]);
            ffma2(s1, wo[pp+1], hp1[(pp+1)*NB]);
            ffma2(s2, wo[pp+2], hp1[(pp+2)*NB]);
            ffma2(s3, wo[pp+3], hp1[(pp+3)*NB]);
        }
        float y = (sum2(s0) + sum2(s1)) + (sum2(s2) + sum2(s3));
        orow[TSTEPS-1] = fmaxf(y, 0.0f);
    }
    asm volatile("barrier.cluster.arrive.aligned;" ::: "memory");
    asm volatile("barrier.cluster.wait.aligned;"   ::: "memory");
}

extern "C" void kernel_launch(void* const* d_in, const int* in_sizes, int n_in,
                              void* d_out, int out_size) {
    (void)in_sizes; (void)n_in; (void)out_size;
    const float* x    = (const float*)d_in[0];
    const float* Wih0 = (const float*)d_in[1];
    const float* Whh0 = (const float*)d_in[2];
    const float* bih0 = (const float*)d_in[3];
    const float* bhh0 = (const float*)d_in[4];
    const float* Wih1 = (const float*)d_in[5];
    const float* Whh1 = (const float*)d_in[6];
    const float* bih1 = (const float*)d_in[7];
    const float* bhh1 = (const float*)d_in[8];
    const float* Wout = (const float*)d_in[9];
    const float* bout = (const float*)d_in[10];
    float* out = (float*)d_out;

    const int xp_smem = 2*IDIM*XP_LD*4;
    cudaFuncSetAttribute(xproj_kernel,
                         cudaFuncAttributeMaxDynamicSharedMemorySize, xp_smem);
    dim3 xg(BATCH/128, 640/128, TSTEPS);
    xproj_kernel<<<xg, XP_THREADS, xp_smem>>>(x, Wih0, bih0, bhh0);

    cudaFuncSetAttribute(lstm2_kernel,
                         cudaFuncAttributeMaxDynamicSharedMemorySize, SMEM_BYTES);
    lstm2_kernel<<<GRIDN, NTH, SMEM_BYTES>>>(Whh0, Wih1, Whh1,
                                             bih1, bhh1, Wout, bout, out);
}

// round 16
// speedup vs baseline: 1.0048x; 1.0048x over previous
#include <cuda_runtime.h>
#include <cstdint>
#include <cstddef>

typedef unsigned long long ull;

// 2-layer LSTM, B=512 T=1024 I=80 H=160, fp32.
// Kernel 1 (xproj): X0[t][row][b] = x @ W_ih0^T + b_ih0 + b_hh0.
// Kernel 2 (lstm2): persistent 8-CTA-cluster recurrence, 640 threads
//   (20 warps, 5/SMSP). Warp w owns gate row w of each quarter (4 rows,
//   one h row per layer). Weight slices SMEM-resident; h replicated per
//   rank (k-pair layout); h0 double-buffered. 2 rendezvous per step
//   (R0, R1; count 8; stores -> __syncthreads -> tid0 arrive.release).

#define HDIM   160
#define IDIM   80
#define TSTEPS 1024
#define BATCH  512
#define CLUSTER 8
#define HS 20
#define GS 80
#define NB 32
#define NTH 640        // 20 warps
#define NCLUS 16
#define GRIDN (NCLUS*CLUSTER)

__device__ float g_X0[(size_t)TSTEPS * 640 * BATCH];

// ---- lstm2 shared layout (float offsets) ----
#define OFF_W0   0        // W_hh0 slice [GS][HDIM]
#define OFF_WH1  12800    // W_hh1 slice [GS][HDIM]
#define OFF_WI1  25600    // W_ih1 slice [GS][HDIM]
#define OFF_H0A  38400    // h0 buf0, k-pairs [80][NB] (ull)
#define OFF_H0B  43520    // h0 buf1
#define OFF_H1   48640    // h1 (single buffer)
#define OFF_WOUT 53760    // W_out [160]
#define OFF_B1   53920    // fused bias layer1 slice [GS]
#define OFF_MBAR 54000    // 2 mbarriers (u64)
#define SMEM_FLOATS 54008
#define SMEM_BYTES (SMEM_FLOATS*4)   // 216032 B

#define MB_R0 (OFF_MBAR*4 + 0)   // h0(t) published (count 8)
#define MB_R1 (OFF_MBAR*4 + 8)   // h1(t) published (count 8)

__device__ __forceinline__ uint32_t smem_u32(const void* p){
    uint32_t a;
    asm("{ .reg .u64 t; cvta.to.shared.u64 t, %1; cvt.u32.u64 %0, t; }"
        : "=r"(a) : "l"(p));
    return a;
}
__device__ __forceinline__ uint32_t mapa_rank(uint32_t addr, uint32_t r){
    uint32_t d;
    asm("mapa.shared::cluster.u32 %0, %1, %2;" : "=r"(d) : "r"(addr), "r"(r));
    return d;
}
__device__ __forceinline__ void st_cluster_f32(uint32_t addr, float v){
    asm volatile("st.shared::cluster.f32 [%0], %1;" :: "r"(addr), "f"(v));
}
__device__ __forceinline__ uint32_t ctarank(){
    uint32_t r; asm("mov.u32 %0, %%cluster_ctarank;" : "=r"(r)); return r;
}
__device__ __forceinline__ void mbar_init(uint32_t addr, uint32_t cnt){
    asm volatile("mbarrier.init.shared.b64 [%0], %1;" :: "r"(addr), "r"(cnt)
                 : "memory");
}
__device__ __forceinline__ void mbar_arrive_all(uint32_t local_addr){
    #pragma unroll
    for (uint32_t r = 0; r < CLUSTER; r++){
        uint32_t ra = mapa_rank(local_addr, r);
        asm volatile(
            "mbarrier.arrive.release.cluster.shared::cluster.b64 _, [%0];"
            :: "r"(ra) : "memory");
    }
}
__device__ __forceinline__ void mbar_wait(uint32_t addr, uint32_t parity){
    uint32_t done;
    asm volatile(
        "{ .reg .pred p;\n\t"
        "mbarrier.try_wait.parity.acquire.cluster.shared::cta.b64 p, [%1], %2;\n\t"
        "selp.b32 %0, 1, 0, p; }"
        : "=r"(done) : "r"(addr), "r"(parity) : "memory");
    while (!done){
        asm volatile(
            "{ .reg .pred p;\n\t"
            "mbarrier.try_wait.parity.acquire.cluster.shared::cta.b64 p, [%1], %2, 0x989680;\n\t"
            "selp.b32 %0, 1, 0, p; }"
            : "=r"(done) : "r"(addr), "r"(parity) : "memory");
    }
}

__device__ __forceinline__ void ffma2(ull &a, ull b, ull c){
    asm("fma.rn.f32x2 %0, %1, %2, %0;" : "+l"(a) : "l"(b), "l"(c));
}
__device__ __forceinline__ ull pack2(float lo, float hi){
    ull r; asm("mov.b64 %0, {%1,%2};" : "=l"(r) : "f"(lo), "f"(hi)); return r;
}
__device__ __forceinline__ float sum2(ull v){
    float lo, hi; asm("mov.b64 {%0,%1}, %2;" : "=f"(lo), "=f"(hi) : "l"(v));
    return lo + hi;
}
__device__ __forceinline__ float sigm(float x){
    return __fdividef(1.0f, 1.0f + __expf(-x));
}
__device__ __forceinline__ float tanhfast(float x){
    return 2.0f*__fdividef(1.0f, 1.0f + __expf(-2.0f*x)) - 1.0f;
}

// acc[q] (f32x2 even/odd-k partials) += W[(q*HS+w)][:] . h[:], K elements.
// W warp-uniform LDS.128, h lane LDS.64, next iter's loads pipelined.
template<int K>
__device__ __forceinline__ void mm4h(ull acc[4], const float* __restrict__ Wsm,
                                     int w, const ull* __restrict__ hp){
    const ulonglong2* W[4];
    #pragma unroll
    for (int q = 0; q < 4; q++)
        W[q] = reinterpret_cast<const ulonglong2*>(Wsm + (q*HS + w)*K);
    ull h01 = hp[0], h23 = hp[NB];
    ulonglong2 wv[4];
    #pragma unroll
    for (int q = 0; q < 4; q++) wv[q] = W[q][0];
    #pragma unroll 8
    for (int kk = 0; kk < K/4; kk++){
        ull n01 = 0, n23 = 0;
        ulonglong2 nw[4];
        if (kk + 1 < K/4){
            n01 = hp[(2*kk+2)*NB]; n23 = hp[(2*kk+3)*NB];
            #pragma unroll
            for (int q = 0; q < 4; q++) nw[q] = W[q][kk+1];
        }
        #pragma unroll
        for (int q = 0; q < 4; q++){
            ffma2(acc[q], wv[q].x, h01);
            ffma2(acc[q], wv[q].y, h23);
        }
        h01 = n01; h23 = n23;
        #pragma unroll
        for (int q = 0; q < 4; q++) wv[q] = nw[q];
    }
}

// ============ kernel 1: X0 = x @ W_ih0^T + bias ============
#define XP_THREADS 256
#define XP_LD 132

__global__ __launch_bounds__(XP_THREADS)
void xproj_kernel(const float* __restrict__ x,
                  const float* __restrict__ Wih0,
                  const float* __restrict__ bih0,
                  const float* __restrict__ bhh0)
{
    extern __shared__ float s[];
    float* WT = s;
    float* XT = s + IDIM*XP_LD;
    const int t = blockIdx.z;
    const int rowbase = blockIdx.y * 128;
    const int bbase   = blockIdx.x * 128;

    for (int idx = threadIdx.x; idx < 128*IDIM; idx += XP_THREADS){
        int r = idx / IDIM, k = idx - r*IDIM;
        WT[k*XP_LD + r] = Wih0[(rowbase + r)*IDIM + k];
    }
    for (int idx = threadIdx.x; idx < 128*IDIM; idx += XP_THREADS){
        int b = idx / IDIM, k = idx - b*IDIM;
        XT[k*XP_LD + b] = x[(size_t)(bbase + b)*(TSTEPS*IDIM)
                            + (size_t)t*IDIM + k];
    }
    __syncthreads();

    const int brow = threadIdx.x >> 4;
    const int bcol = threadIdx.x & 15;
    float acc[8][8] = {};
    for (int k = 0; k < IDIM; k++){
        float wr[8], xr[8];
        #pragma unroll
        for (int i = 0; i < 8; i++) wr[i] = WT[k*XP_LD + brow + 16*i];
        #pragma unroll
        for (int j = 0; j < 8; j++) xr[j] = XT[k*XP_LD + bcol + 16*j];
        #pragma unroll
        for (int i = 0; i < 8; i++)
            #pragma unroll
            for (int j = 0; j < 8; j++)
                acc[i][j] += wr[i]*xr[j];
    }
    #pragma unroll
    for (int i = 0; i < 8; i++){
        int row = rowbase + brow + 16*i;
        float bias = bih0[row] + bhh0[row];
        float* dst = g_X0 + ((size_t)t*640 + row)*BATCH + bbase;
        #pragma unroll
        for (int j = 0; j < 8; j++)
            dst[bcol + 16*j] = acc[i][j] + bias;
    }
}

// ============ kernel 2: recurrence ============
__global__ void __cluster_dims__(CLUSTER,1,1) __launch_bounds__(NTH,1)
lstm2_kernel(const float* __restrict__ Whh0,
             const float* __restrict__ Wih1, const float* __restrict__ Whh1,
             const float* __restrict__ bih1, const float* __restrict__ bhh1,
             const float* __restrict__ Wout, const float* __restrict__ bout,
             float* __restrict__ out)
{
    extern __shared__ float sm[];
    const int tid  = threadIdx.x;
    const int lane = tid & 31;
    const int w    = tid >> 5;        // 0..19; owns gate row w per quarter
    const uint32_t rank = ctarank();
    const int cidx = blockIdx.x / CLUSTER;
    const int b0g  = cidx * NB;
    const int hb   = (int)rank * HS;
    const uint32_t smb = smem_u32(sm);

    // persistent weight slices
    for (int idx = tid; idx < GS*HDIM; idx += NTH){
        int lr = idx / HDIM, k = idx - lr*HDIM;
        int q = lr / HS, j = lr - q*HS;
        int grow = q*HDIM + hb + j;           // pytorch gate order i,f,g,o
        sm[OFF_W0  + idx] = Whh0[grow*HDIM + k];
        sm[OFF_WH1 + idx] = Whh1[grow*HDIM + k];
        sm[OFF_WI1 + idx] = Wih1[grow*HDIM + k];
    }
    for (int idx = tid; idx < GS; idx += NTH){
        int q = idx / HS, j = idx - q*HS;
        int grow = q*HDIM + hb + j;
        sm[OFF_B1 + idx] = bih1[grow] + bhh1[grow];
    }
    for (int idx = tid; idx < HDIM; idx += NTH) sm[OFF_WOUT + idx] = Wout[idx];
    for (int idx = tid; idx < 3*HDIM*NB; idx += NTH) sm[OFF_H0A + idx] = 0.0f;
    if (tid == 0){
        mbar_init(smb + MB_R0, CLUSTER);
        mbar_init(smb + MB_R1, CLUSTER);
    }
    float c0 = 0.f, c1 = 0.f;
    __syncthreads();
    asm volatile("barrier.cluster.arrive.aligned;" ::: "memory");
    asm volatile("barrier.cluster.wait.aligned;"   ::: "memory");
    // prime R1 phase 0 (h1(-1)=0 already staged)
    if (tid == 0) mbar_arrive_all(smb + MB_R1);

    // this thread's h element: row g = hb+w, batch lane.
    // k-pair float offset within a buffer: ((g>>1)*NB + lane)*2 + (g&1)
    const int g = hb + w;
    const uint32_t eoff = (uint32_t)(((g >> 1)*NB + lane)*2 + (g & 1))*4u;
    const uint32_t oA = smb + OFF_H0A*4 + eoff;
    const uint32_t oB = smb + OFF_H0B*4 + eoff;
    const uint32_t o1 = smb + OFF_H1*4  + eoff;

    float b1r[4];
    #pragma unroll
    for (int q = 0; q < 4; q++) b1r[q] = sm[OFF_B1 + q*HS + w];

    // X0 row pointers for this thread's 4 gate rows
    const float* xp[4];
    #pragma unroll
    for (int q = 0; q < 4; q++){
        int grow = q*HDIM + hb + w;
        xp[q] = g_X0 + (size_t)grow*BATCH + b0g + lane;
    }

    const ull* h0A = reinterpret_cast<const ull*>(&sm[OFF_H0A]) + lane;
    const ull* h0B = reinterpret_cast<const ull*>(&sm[OFF_H0B]) + lane;
    const ull* hp1 = reinterpret_cast<const ull*>(&sm[OFF_H1])  + lane;
    const ull* wo  = reinterpret_cast<const ull*>(&sm[OFF_WOUT]);
    const float boutv = bout[0];
    float* const orow = out + (size_t)(b0g + lane)*TSTEPS;

    for (int t = 0; t < TSTEPS; t++){
        const uint32_t par = (uint32_t)(t & 1);
        const int p = t & 1;
        const ull* hp0_old = p ? h0A : h0B;
        const ull* hp0_new = p ? h0B : h0A;
        const uint32_t ow  = p ? oB : oA;

        // 1: X0 gate seeds (LDG in flight through segment 2)
        float xg[4];
        #pragma unroll
        for (int q = 0; q < 4; q++) xg[q] = xp[q][(size_t)t*640*BATCH];

        // 2: layer-0 recurrent, reads h0(t-1)
        ull acc[4];
        #pragma unroll
        for (int q = 0; q < 4; q++) acc[q] = pack2(xg[q], 0.f);
        mm4h<HDIM>(acc, &sm[OFF_W0], w, hp0_old);

        // 3: h1(t-1) ready (published at end of step t-1; hidden behind 2)
        mbar_wait(smb + MB_R1, par);

        // 4: output head for t-1 (reads h1(t-1); ordered before h1(t)
        //    stores via this CTA's R0 participation below)
        if (w == 0 && t > 0){
            ull s0 = pack2(boutv, 0.f), s1 = 0, s2 = 0, s3 = 0;
            #pragma unroll 10
            for (int pp = 0; pp < HDIM/2; pp += 4){
                ffma2(s0, wo[pp  ], hp1[(pp  )*NB]);
                ffma2(s1, wo[pp+1], hp1[(pp+1)*NB]);
                ffma2(s2, wo[pp+2], hp1[(pp+2)*NB]);
                ffma2(s3, wo[pp+3], hp1[(pp+3)*NB]);
            }
            float y = (sum2(s0) + sum2(s1)) + (sum2(s2) + sum2(s3));
            orow[t-1] = fmaxf(y, 0.0f);
        }

        // 5: layer-1 recurrent W_hh1 . h1(t-1) — precedes h0 publish
        ull a1c[4];
        #pragma unroll
        for (int q = 0; q < 4; q++) a1c[q] = pack2(b1r[q], 0.f);
        mm4h<HDIM>(a1c, &sm[OFF_WH1], w, hp1);

        // 6: layer-0 activations (one h row per thread)
        float hn0;
        {
            float gi = sigm(sum2(acc[0])), gf = sigm(sum2(acc[1]));
            float gg = tanhfast(sum2(acc[2])), go = sigm(sum2(acc[3]));
            c0 = gf*c0 + gi*gg;  hn0 = go*tanhfast(c0);
        }

        // 7: publish h0(t) -> buf t&1 (stores -> sync -> tid0 arrive)
        #pragma unroll
        for (uint32_t r = 0; r < CLUSTER; r++)
            st_cluster_f32(mapa_rank(ow, r), hn0);
        __syncthreads();
        if (tid == 0) mbar_arrive_all(smb + MB_R0);

        // 8: h0(t) visible everywhere
        mbar_wait(smb + MB_R0, par);

        // 9: W_ih1 . h0(t)
        mm4h<HDIM>(a1c, &sm[OFF_WI1], w, hp0_new);

        // 10: layer-1 activations
        float hn1;
        {
            float gi = sigm(sum2(a1c[0])), gf = sigm(sum2(a1c[1]));
            float gg = tanhfast(sum2(a1c[2])), go = sigm(sum2(a1c[3]));
            c1 = gf*c1 + gi*gg;  hn1 = go*tanhfast(c1);
        }

        // 11: publish h1(t) (single buffer; WAR covered by R0(t))
        #pragma unroll
        for (uint32_t r = 0; r < CLUSTER; r++)
            st_cluster_f32(mapa_rank(o1, r), hn1);
        __syncthreads();
        if (tid == 0) mbar_arrive_all(smb + MB_R1);
    }

    // final head: h1(T-1)
    mbar_wait(smb + MB_R1, (uint32_t)(TSTEPS & 1));
    if (w == 0){
        ull s0 = pack2(boutv, 0.f), s1 = 0, s2 = 0, s3 = 0;
        #pragma unroll 10
        for (int pp = 0; pp < HDIM/2; pp += 4){
            ffma2(s0, wo[pp  ], hp1[(pp  )*NB]);
            ffma2(s1, wo[pp+1], hp1[(pp+1)*NB]);
            ffma2(s2, wo[pp+2], hp1[(pp+2)*NB]);
            ffma2(s3, wo[pp+3], hp1[(pp+3)*NB]);
        }
        float y = (sum2(s0) + sum2(s1)) + (sum2(s2) + sum2(s3));
        orow[TSTEPS-1] = fmaxf(y, 0.0f);
    }
    asm volatile("barrier.cluster.arrive.aligned;" ::: "memory");
    asm volatile("barrier.cluster.wait.aligned;"   ::: "memory");
}

extern "C" void kernel_launch(void* const* d_in, const int* in_sizes, int n_in,
                              void* d_out, int out_size) {
    (void)in_sizes; (void)n_in; (void)out_size;
    const float* x    = (const float*)d_in[0];
    const float* Wih0 = (const float*)d_in[1];
    const float* Whh0 = (const float*)d_in[2];
    const float* bih0 = (const float*)d_in[3];
    const float* bhh0 = (const float*)d_in[4];
    const float* Wih1 = (const float*)d_in[5];
    const float* Whh1 = (const float*)d_in[6];
    const float* bih1 = (const float*)d_in[7];
    const float* bhh1 = (const float*)d_in[8];
    const float* Wout = (const float*)d_in[9];
    const float* bout = (const float*)d_in[10];
    float* out = (float*)d_out;

    const int xp_smem = 2*IDIM*XP_LD*4;
    cudaFuncSetAttribute(xproj_kernel,
                         cudaFuncAttributeMaxDynamicSharedMemorySize, xp_smem);
    dim3 xg(BATCH/128, 640/128, TSTEPS);
    xproj_kernel<<<xg, XP_THREADS, xp_smem>>>(x, Wih0, bih0, bhh0);

    cudaFuncSetAttribute(lstm2_kernel,
                         cudaFuncAttributeMaxDynamicSharedMemorySize, SMEM_BYTES);
    lstm2_kernel<<<GRIDN, NTH, SMEM_BYTES>>>(Whh0, Wih1, Whh1,
                                             bih1, bhh1, Wout, bout, out);
}

// round 17
// speedup vs baseline: 1.5337x; 1.5263x over previous
#include <cuda_runtime.h>
#include <cstdint>
#include <cstddef>

typedef unsigned long long ull;

// 2-layer LSTM, B=512 T=1024 I=80 H=160, fp32 — NO clusters.
// K1 xproj: X0[t][row][b] = x @ W_ih0^T + b_ih0 + b_hh0   (precompute)
// K2 wprep: rearrange recurrent weights to [m][kq][640][4] so each
//           warp LDG.128 is exactly one 128B line.
// K3 lstm2: 128 independent CTAs x 640 threads; CTA owns 4 batch elems.
//           Weights streamed from L2 every step (157MB/step chip-wide,
//           L2-resident). h0/h1 double-buffered in SMEM; 2 __syncthreads
//           per step; zero inter-CTA communication.

#define HDIM   160
#define IDIM   80
#define TSTEPS 1024
#define BATCH  512
#define NTH    640      // thread: r = tid>>2 (0..159), jb = tid&3
#define GRIDN  128      // 128 CTAs x 4 batch = 512
#define HP     168      // padded h row stride (floats), 672B (16B mult)

__device__ float g_X0[(size_t)TSTEPS * 640 * BATCH];
__device__ float g_Wt[3 * 40 * 640 * 4];   // [m][kq][row][kk]

__device__ __forceinline__ void ffma2(ull &a, ull b, ull c){
    asm("fma.rn.f32x2 %0, %1, %2, %0;" : "+l"(a) : "l"(b), "l"(c));
}
__device__ __forceinline__ ull pack2(float lo, float hi){
    ull r; asm("mov.b64 %0, {%1,%2};" : "=l"(r) : "f"(lo), "f"(hi)); return r;
}
__device__ __forceinline__ float sum2(ull v){
    float lo, hi; asm("mov.b64 {%0,%1}, %2;" : "=f"(lo), "=f"(hi) : "l"(v));
    return lo + hi;
}
__device__ __forceinline__ float sigm(float x){
    return __fdividef(1.0f, 1.0f + __expf(-x));
}
__device__ __forceinline__ float tanhfast(float x){
    return 2.0f*__fdividef(1.0f, 1.0f + __expf(-2.0f*x)) - 1.0f;
}

// acc[q] (f32x2 even/odd-k partials) += W[q*160+r][:] . h[:]  (K=160)
// W: one 128B-coalesced LDG.128 per (q,kq) (8 rows x 16B, 4-lane dup).
// h: LDS.128 broadcast (4 distinct addrs per warp).
__device__ __forceinline__ void mm4(ull acc[4], const float4* __restrict__ Wp,
                                    int r, const ull* __restrict__ hb){
    const float4* W0 = Wp + r;
    const float4* W1 = Wp + 160 + r;
    const float4* W2 = Wp + 320 + r;
    const float4* W3 = Wp + 480 + r;
    #pragma unroll 4
    for (int kq = 0; kq < 40; kq++){
        float4 w0 = W0[kq*640];
        float4 w1 = W1[kq*640];
        float4 w2 = W2[kq*640];
        float4 w3 = W3[kq*640];
        ulonglong2 h2 = *reinterpret_cast<const ulonglong2*>(hb + kq*2);
        const ull* u;
        u = reinterpret_cast<const ull*>(&w0);
        ffma2(acc[0], u[0], h2.x); ffma2(acc[0], u[1], h2.y);
        u = reinterpret_cast<const ull*>(&w1);
        ffma2(acc[1], u[0], h2.x); ffma2(acc[1], u[1], h2.y);
        u = reinterpret_cast<const ull*>(&w2);
        ffma2(acc[2], u[0], h2.x); ffma2(acc[2], u[1], h2.y);
        u = reinterpret_cast<const ull*>(&w3);
        ffma2(acc[3], u[0], h2.x); ffma2(acc[3], u[1], h2.y);
    }
}

// ============ kernel 1: X0 = x @ W_ih0^T + bias (unchanged, proven) ======
#define XP_THREADS 256
#define XP_LD 132

__global__ __launch_bounds__(XP_THREADS)
void xproj_kernel(const float* __restrict__ x,
                  const float* __restrict__ Wih0,
                  const float* __restrict__ bih0,
                  const float* __restrict__ bhh0)
{
    extern __shared__ float s[];
    float* WT = s;
    float* XT = s + IDIM*XP_LD;
    const int t = blockIdx.z;
    const int rowbase = blockIdx.y * 128;
    const int bbase   = blockIdx.x * 128;

    for (int idx = threadIdx.x; idx < 128*IDIM; idx += XP_THREADS){
        int r = idx / IDIM, k = idx - r*IDIM;
        WT[k*XP_LD + r] = Wih0[(rowbase + r)*IDIM + k];
    }
    for (int idx = threadIdx.x; idx < 128*IDIM; idx += XP_THREADS){
        int b = idx / IDIM, k = idx - b*IDIM;
        XT[k*XP_LD + b] = x[(size_t)(bbase + b)*(TSTEPS*IDIM)
                            + (size_t)t*IDIM + k];
    }
    __syncthreads();

    const int brow = threadIdx.x >> 4;
    const int bcol = threadIdx.x & 15;
    float acc[8][8] = {};
    for (int k = 0; k < IDIM; k++){
        float wr[8], xr[8];
        #pragma unroll
        for (int i = 0; i < 8; i++) wr[i] = WT[k*XP_LD + brow + 16*i];
        #pragma unroll
        for (int j = 0; j < 8; j++) xr[j] = XT[k*XP_LD + bcol + 16*j];
        #pragma unroll
        for (int i = 0; i < 8; i++)
            #pragma unroll
            for (int j = 0; j < 8; j++)
                acc[i][j] += wr[i]*xr[j];
    }
    #pragma unroll
    for (int i = 0; i < 8; i++){
        int row = rowbase + brow + 16*i;
        float bias = bih0[row] + bhh0[row];
        float* dst = g_X0 + ((size_t)t*640 + row)*BATCH + bbase;
        #pragma unroll
        for (int j = 0; j < 8; j++)
            dst[bcol + 16*j] = acc[i][j] + bias;
    }
}

// ============ kernel 2: weight rearrange ============
__global__ __launch_bounds__(128)
void wprep_kernel(const float* __restrict__ Whh0,
                  const float* __restrict__ Wih1,
                  const float* __restrict__ Whh1)
{
    const float* src = (blockIdx.y == 0) ? Whh0 :
                       (blockIdx.y == 1) ? Wih1 : Whh1;
    int row = blockIdx.x * 128 + threadIdx.x;   // 5 blocks x 128 = 640
    const float4* s4 = reinterpret_cast<const float4*>(src + row*HDIM);
    float4* dst = reinterpret_cast<float4*>(g_Wt) + (size_t)blockIdx.y*40*640;
    #pragma unroll 8
    for (int kq = 0; kq < 40; kq++)
        dst[kq*640 + row] = s4[kq];
}

// ============ kernel 3: recurrence ============
__global__ __launch_bounds__(NTH, 1)
void lstm2_kernel(const float* __restrict__ bih1,
                  const float* __restrict__ bhh1,
                  const float* __restrict__ Wout,
                  const float* __restrict__ bout,
                  float* __restrict__ out)
{
    __shared__ __align__(16) float smh[4*4*HP];   // h0A,h0B,h1A,h1B [4][HP]
    __shared__ __align__(16) float smwo[HDIM];

    const int tid  = threadIdx.x;
    const int lane = tid & 31;
    const int r    = tid >> 2;       // h-row 0..159
    const int jb   = tid & 3;        // local batch 0..3
    const int b0g  = blockIdx.x * 4;

    for (int i = tid; i < 4*4*HP; i += NTH) smh[i] = 0.0f;
    for (int i = tid; i < HDIM;  i += NTH) smwo[i] = Wout[i];

    // layer-1 fused bias for this thread's 4 gate rows
    float b1r[4];
    #pragma unroll
    for (int q = 0; q < 4; q++){
        int grow = q*HDIM + r;
        b1r[q] = bih1[grow] + bhh1[grow];
    }
    // X0 pointers (4 gates)
    const float* xq[4];
    #pragma unroll
    for (int q = 0; q < 4; q++)
        xq[q] = g_X0 + (size_t)(q*HDIM + r)*BATCH + b0g + jb;

    const float4* Wt0 = reinterpret_cast<const float4*>(g_Wt);
    const float4* Wt1 = Wt0 + 40*640;
    const float4* Wt2 = Wt1 + 40*640;

    float* h0r = smh;            // h0(t-1)
    float* h0w = smh + 4*HP;     // h0(t)
    float* h1r = smh + 8*HP;     // h1(t-1)
    float* h1w = smh + 12*HP;    // h1(t)

    float c0 = 0.f, c1 = 0.f;
    const float boutv = bout[0];
    __syncthreads();

    for (int t = 0; t < TSTEPS; t++){
        // x-projection seeds (LDG in flight during mm0)
        float xs[4];
        #pragma unroll
        for (int q = 0; q < 4; q++) xs[q] = xq[q][(size_t)t*640*BATCH];

        // layer 0: W_hh0 . h0(t-1)
        ull a0[4] = {0,0,0,0};
        mm4(a0, Wt0, r, reinterpret_cast<const ull*>(h0r + jb*HP));

        float hn0;
        {
            float gi = sigm(sum2(a0[0]) + xs[0]);
            float gf = sigm(sum2(a0[1]) + xs[1]);
            float gg = tanhfast(sum2(a0[2]) + xs[2]);
            float go = sigm(sum2(a0[3]) + xs[3]);
            c0 = gf*c0 + gi*gg;  hn0 = go*tanhfast(c0);
        }
        h0w[jb*HP + r] = hn0;
        __syncthreads();                    // h0(t) visible CTA-wide

        // layer 1: W_ih1 . h0(t) + W_hh1 . h1(t-1)
        ull a1[4];
        #pragma unroll
        for (int q = 0; q < 4; q++) a1[q] = pack2(b1r[q], 0.f);
        mm4(a1, Wt1, r, reinterpret_cast<const ull*>(h0w + jb*HP));
        mm4(a1, Wt2, r, reinterpret_cast<const ull*>(h1r + jb*HP));

        float hn1;
        {
            float gi = sigm(sum2(a1[0]));
            float gf = sigm(sum2(a1[1]));
            float gg = tanhfast(sum2(a1[2]));
            float go = sigm(sum2(a1[3]));
            c1 = gf*c1 + gi*gg;  hn1 = go*tanhfast(c1);
        }
        h1w[jb*HP + r] = hn1;
        __syncthreads();                    // h1(t) visible CTA-wide

        // output head: warp 0. lane = (b = lane>>3, k-seg = lane&7)
        if (tid < 32){
            int b   = lane >> 3;
            int seg = lane & 7;             // 20 k-values per segment
            const ull* hrow = reinterpret_cast<const ull*>(h1w + b*HP);
            const ull* wo   = reinterpret_cast<const ull*>(smwo);
            ull ph = 0;
            #pragma unroll
            for (int kq = 0; kq < 5; kq++){
                int kp = seg*10 + kq*2;
                ffma2(ph, wo[kp  ], hrow[kp  ]);
                ffma2(ph, wo[kp+1], hrow[kp+1]);
            }
            float p = sum2(ph);
            p += __shfl_down_sync(0xffffffffu, p, 4, 8);
            p += __shfl_down_sync(0xffffffffu, p, 2, 8);
            p += __shfl_down_sync(0xffffffffu, p, 1, 8);
            if (seg == 0)
                out[(size_t)(b0g + b)*TSTEPS + t] = fmaxf(p + boutv, 0.0f);
        }

        // swap double buffers
        float* tmp;
        tmp = h0r; h0r = h0w; h0w = tmp;
        tmp = h1r; h1r = h1w; h1w = tmp;
    }
}

extern "C" void kernel_launch(void* const* d_in, const int* in_sizes, int n_in,
                              void* d_out, int out_size) {
    (void)in_sizes; (void)n_in; (void)out_size;
    const float* x    = (const float*)d_in[0];
    const float* Wih0 = (const float*)d_in[1];
    const float* Whh0 = (const float*)d_in[2];
    const float* bih0 = (const float*)d_in[3];
    const float* bhh0 = (const float*)d_in[4];
    const float* Wih1 = (const float*)d_in[5];
    const float* Whh1 = (const float*)d_in[6];
    const float* bih1 = (const float*)d_in[7];
    const float* bhh1 = (const float*)d_in[8];
    const float* Wout = (const float*)d_in[9];
    const float* bout = (const float*)d_in[10];
    float* out = (float*)d_out;

    const int xp_smem = 2*IDIM*XP_LD*4;
    cudaFuncSetAttribute(xproj_kernel,
                         cudaFuncAttributeMaxDynamicSharedMemorySize, xp_smem);
    dim3 xg(BATCH/128, 640/128, TSTEPS);
    xproj_kernel<<<xg, XP_THREADS, xp_smem>>>(x, Wih0, bih0, bhh0);

    dim3 wg(5, 3);
    wprep_kernel<<<wg, 128>>>(Whh0, Wih1, Whh1);

    lstm2_kernel<<<GRIDN, NTH>>>(bih1, bhh1, Wout, bout, out);
}